// round 13
// baseline (speedup 1.0000x reference)
#include <cuda_runtime.h>
#include <cuda_bf16.h>
#include <math.h>
#include <stdint.h>

// Problem constants
#define BATCH 4
#define SEQ   2048
#define EMB   1024
#define HEADS 16
#define DK    64
#define MROWS (BATCH*SEQ)   // 8192
#define NELEM (MROWS*EMB)

// ---------------------------------------------------------------------------
// Scratch (static device arrays; no allocations allowed).
// g_Qp/g_Kp/g_Vp (fp32-sized) are aliased as PAIRS of bf16 arrays (hi, lo).
// ---------------------------------------------------------------------------
__device__ float g_Qp[NELEM];
__device__ float g_Kp[NELEM];
__device__ float g_Vp[NELEM];

__device__ __nv_bfloat16 g_xh[NELEM];   // x split hi
__device__ __nv_bfloat16 g_xl[NELEM];   // x split lo
__device__ __nv_bfloat16 g_ah[NELEM];   // attn out split hi
__device__ __nv_bfloat16 g_al[NELEM];   // attn out split lo
__device__ __nv_bfloat16 g_wh[4][EMB * EMB];  // W^T split hi  [n][k]
__device__ __nv_bfloat16 g_wl[4][EMB * EMB];  // W^T split lo  [n][k]

// ---------------------------------------------------------------------------
// PTX helpers (sm_80-era only; legal on plain sm_103 PTX target)
// ---------------------------------------------------------------------------
__device__ __forceinline__ uint32_t s2u(const void* p) {
    uint32_t a;
    asm("{ .reg .u64 t; cvta.to.shared.u64 t, %1; cvt.u32.u64 %0, t; }"
        : "=r"(a) : "l"(p));
    return a;
}

__device__ __forceinline__ void cpasync16(uint32_t dst, const void* src) {
    asm volatile("cp.async.cg.shared.global [%0], [%1], 16;"
                 :: "r"(dst), "l"(src));
}
#define CP_COMMIT() asm volatile("cp.async.commit_group;" ::: "memory")

__device__ __forceinline__ void ldx4(uint32_t* r, uint32_t addr) {
    asm volatile("ldmatrix.sync.aligned.m8n8.x4.shared.b16 {%0,%1,%2,%3}, [%4];"
                 : "=r"(r[0]), "=r"(r[1]), "=r"(r[2]), "=r"(r[3])
                 : "r"(addr));
}

__device__ __forceinline__ void ldx4t(uint32_t* r, uint32_t addr) {
    asm volatile("ldmatrix.sync.aligned.m8n8.x4.trans.shared.b16 {%0,%1,%2,%3}, [%4];"
                 : "=r"(r[0]), "=r"(r[1]), "=r"(r[2]), "=r"(r[3])
                 : "r"(addr));
}

__device__ __forceinline__ void mma_bf16(float* d, const uint32_t* a,
                                         uint32_t b0, uint32_t b1) {
    asm volatile("mma.sync.aligned.m16n8k16.row.col.f32.bf16.bf16.f32 "
                 "{%0,%1,%2,%3}, {%4,%5,%6,%7}, {%8,%9}, {%0,%1,%2,%3};"
                 : "+f"(d[0]), "+f"(d[1]), "+f"(d[2]), "+f"(d[3])
                 : "r"(a[0]), "r"(a[1]), "r"(a[2]), "r"(a[3]),
                   "r"(b0), "r"(b1));
}

// pack two fp32 into bf16x2 (lo = first element, little-endian low half)
__device__ __forceinline__ uint32_t packbf(float lo, float hi) {
    uint32_t r;
    asm("cvt.rn.bf16x2.f32 %0, %1, %2;" : "=r"(r) : "f"(hi), "f"(lo));
    return r;
}
// bf16x2 halves back to fp32 (exact: bf16 -> fp32 is a 16-bit shift)
__device__ __forceinline__ float bfloat_lo(uint32_t p) { return __uint_as_float(p << 16); }
__device__ __forceinline__ float bfloat_hi(uint32_t p) { return __uint_as_float(p & 0xffff0000u); }

__device__ __forceinline__ float ex2f(float x) {
    float y;
    asm("ex2.approx.ftz.f32 %0, %1;" : "=f"(y) : "f"(x));
    return y;
}

#define NEG_INF __int_as_float(0xff800000)

// ---------------------------------------------------------------------------
// Split kernel: fp32 -> (bf16 hi, bf16 lo residual)
// ---------------------------------------------------------------------------
__global__ void split_kernel(const float* __restrict__ in,
                             __nv_bfloat16* __restrict__ hi,
                             __nv_bfloat16* __restrict__ lo, int n)
{
    int i = (blockIdx.x * blockDim.x + threadIdx.x) * 4;
    if (i >= n) return;
    float4 v = *(const float4*)(in + i);
    uint32_t h01 = packbf(v.x, v.y);
    uint32_t h23 = packbf(v.z, v.w);
    uint32_t l01 = packbf(v.x - bfloat_lo(h01), v.y - bfloat_hi(h01));
    uint32_t l23 = packbf(v.z - bfloat_lo(h23), v.w - bfloat_hi(h23));
    *(uint32_t*)(hi + i)     = h01;
    *(uint32_t*)(hi + i + 2) = h23;
    *(uint32_t*)(lo + i)     = l01;
    *(uint32_t*)(lo + i + 2) = l23;
}

// ---------------------------------------------------------------------------
// Weight transpose + split: Wt[n][k] = split(W[k][n]), 32x32 smem tiles
// ---------------------------------------------------------------------------
__global__ void wsplit_kernel(const float* __restrict__ W,
                              __nv_bfloat16* __restrict__ ht,
                              __nv_bfloat16* __restrict__ lt)
{
    __shared__ float t[32][33];
    const int tx = threadIdx.x, ty = threadIdx.y;      // 32 x 8
    const int n0 = blockIdx.x * 32, k0 = blockIdx.y * 32;
    #pragma unroll
    for (int j = 0; j < 4; j++)
        t[ty + 8 * j][tx] = W[(size_t)(k0 + ty + 8 * j) * EMB + n0 + tx];
    __syncthreads();
    #pragma unroll
    for (int j = 0; j < 4; j++) {
        float v = t[tx][ty + 8 * j];
        __nv_bfloat16 h = __float2bfloat16(v);
        __nv_bfloat16 l = __float2bfloat16(v - __bfloat162float(h));
        size_t o = (size_t)(n0 + ty + 8 * j) * EMB + k0 + tx;
        ht[o] = h;
        lt[o] = l;
    }
}

// ---------------------------------------------------------------------------
// HMMA split-bf16 GEMM core (CTA tile 128x128, BK=32, 2-stage cp.async).
// ---------------------------------------------------------------------------
#define GBK       32
#define NCHUNK    (EMB / GBK)          // 32
#define TILE_B    (128 * 80)           // 10240 B per operand tile
#define STAGE_B   (4 * TILE_B)         // Ah, Al, Bh, Bl = 40960 B
#define GEMM_SMEM (2 * STAGE_B)        // 81920 B

__device__ __forceinline__ void load_chunk(uint32_t st,
    const __nv_bfloat16* Ah, const __nv_bfloat16* Al,
    const __nv_bfloat16* Bh, const __nv_bfloat16* Bl,
    int k0, int tid)
{
    const __nv_bfloat16* srcs[4] = { Ah, Al, Bh, Bl };
    #pragma unroll
    for (int t = 0; t < 4; t++) {
        const char* base = (const char*)srcs[t] + (size_t)k0 * 2;
        #pragma unroll
        for (int j = 0; j < 2; j++) {
            int idx = tid + j * 256;       // 0..511
            int row = idx >> 2;            // 0..127
            int c16 = (idx & 3) * 16;      // 0,16,32,48
            cpasync16(st + t * TILE_B + row * 80 + c16,
                      base + (size_t)row * (EMB * 2) + c16);
        }
    }
}

// Mainloop: computes acc[2][8][4] for tile (bm, bn) of A * B.
__device__ __forceinline__ void gemm_mainloop(
    uint32_t sb, int tid,
    const __nv_bfloat16* Ahb, const __nv_bfloat16* Alb,
    const __nv_bfloat16* Bhb, const __nv_bfloat16* Blb,
    float acc[2][8][4])
{
    const int wid = tid >> 5, l = tid & 31;
    const int wm = wid & 3;
    const int wn = wid >> 2;

    int aoffm[2];
    #pragma unroll
    for (int mi = 0; mi < 2; mi++)
        aoffm[mi] = (wm * 32 + mi * 16 + (l & 15)) * 80 + ((l >> 4) & 1) * 16;
    int boffp[4];
    #pragma unroll
    for (int p = 0; p < 4; p++)
        boffp[p] = (wn * 64 + p * 16 + (l & 7) + ((l >> 4) << 3)) * 80
                 + ((l >> 3) & 1) * 16;

    #pragma unroll
    for (int mi = 0; mi < 2; mi++)
        #pragma unroll
        for (int ni = 0; ni < 8; ni++)
            #pragma unroll
            for (int r = 0; r < 4; r++) acc[mi][ni][r] = 0.f;

    load_chunk(sb + 0 * STAGE_B, Ahb, Alb, Bhb, Blb, 0 * GBK, tid);
    CP_COMMIT();
    load_chunk(sb + 1 * STAGE_B, Ahb, Alb, Bhb, Blb, 1 * GBK, tid);
    CP_COMMIT();

    for (int c = 0; c < NCHUNK; c++) {
        if (c < NCHUNK - 1) asm volatile("cp.async.wait_group 1;" ::: "memory");
        else                asm volatile("cp.async.wait_group 0;" ::: "memory");
        __syncthreads();

        const uint32_t st = sb + (c & 1) * STAGE_B;
        #pragma unroll
        for (int ks = 0; ks < 2; ks++) {
            const uint32_t koff = ks * 32;
            uint32_t ah[2][4], al[2][4];
            #pragma unroll
            for (int mi = 0; mi < 2; mi++) {
                ldx4(ah[mi], st + 0 * TILE_B + aoffm[mi] + koff);
                ldx4(al[mi], st + 1 * TILE_B + aoffm[mi] + koff);
            }
            #pragma unroll
            for (int p = 0; p < 4; p++) {
                uint32_t bh[4], bl[4];
                ldx4(bh, st + 2 * TILE_B + boffp[p] + koff);
                ldx4(bl, st + 3 * TILE_B + boffp[p] + koff);
                #pragma unroll
                for (int mi = 0; mi < 2; mi++) {
                    #pragma unroll
                    for (int sub = 0; sub < 2; sub++) {
                        float* d = acc[mi][p * 2 + sub];
                        const uint32_t b0 = bh[sub * 2], b1 = bh[sub * 2 + 1];
                        mma_bf16(d, ah[mi], b0, b1);
                        mma_bf16(d, ah[mi], bl[sub * 2], bl[sub * 2 + 1]);
                        mma_bf16(d, al[mi], b0, b1);
                    }
                }
            }
        }
        __syncthreads();

        if (c + 2 < NCHUNK) {
            load_chunk(st, Ahb, Alb, Bhb, Blb, (c + 2) * GBK, tid);
            CP_COMMIT();
        }
    }
}

// Fused Q/K/V projection: grid (24, 64); bn>>3 selects weight + output pair.
__global__ void __launch_bounds__(256, 2) gemm_qkv_kernel(
    const __nv_bfloat16* __restrict__ Ah, const __nv_bfloat16* __restrict__ Al,
    const __nv_bfloat16* __restrict__ Wh, const __nv_bfloat16* __restrict__ Wl,
    __nv_bfloat16* __restrict__ q_h, __nv_bfloat16* __restrict__ q_l,
    __nv_bfloat16* __restrict__ k_h, __nv_bfloat16* __restrict__ k_l,
    __nv_bfloat16* __restrict__ v_h, __nv_bfloat16* __restrict__ v_l)
{
    extern __shared__ char smem[];
    const uint32_t sb = s2u(smem);
    const int tid = threadIdx.x;
    const int wid = tid >> 5, l = tid & 31;
    const int bnf = blockIdx.x, bm = blockIdx.y;
    const int widx = bnf >> 3, bn = bnf & 7;

    const __nv_bfloat16* Ahb = Ah + (size_t)bm * 128 * EMB;
    const __nv_bfloat16* Alb = Al + (size_t)bm * 128 * EMB;
    const __nv_bfloat16* Bhb = Wh + (size_t)widx * EMB * EMB + (size_t)bn * 128 * EMB;
    const __nv_bfloat16* Blb = Wl + (size_t)widx * EMB * EMB + (size_t)bn * 128 * EMB;
    __nv_bfloat16* Ch = (widx == 0) ? q_h : (widx == 1) ? k_h : v_h;
    __nv_bfloat16* Cl = (widx == 0) ? q_l : (widx == 1) ? k_l : v_l;

    float acc[2][8][4];
    gemm_mainloop(sb, tid, Ahb, Alb, Bhb, Blb, acc);

    const int wm = wid & 3, wn = wid >> 2;
    const int g = l >> 2, t2 = (l & 3) * 2;
    #pragma unroll
    for (int mi = 0; mi < 2; mi++) {
        #pragma unroll
        for (int ni = 0; ni < 8; ni++) {
            const int row = bm * 128 + wm * 32 + mi * 16 + g;
            const int col = bn * 128 + wn * 64 + ni * 8 + t2;
            const size_t o0 = (size_t)row * EMB + col;
            const size_t o1 = o0 + (size_t)8 * EMB;
            uint32_t h0 = packbf(acc[mi][ni][0], acc[mi][ni][1]);
            uint32_t l0 = packbf(acc[mi][ni][0] - bfloat_lo(h0),
                                 acc[mi][ni][1] - bfloat_hi(h0));
            uint32_t h1 = packbf(acc[mi][ni][2], acc[mi][ni][3]);
            uint32_t l1 = packbf(acc[mi][ni][2] - bfloat_lo(h1),
                                 acc[mi][ni][3] - bfloat_hi(h1));
            *(uint32_t*)(Ch + o0) = h0;
            *(uint32_t*)(Cl + o0) = l0;
            *(uint32_t*)(Ch + o1) = h1;
            *(uint32_t*)(Cl + o1) = l1;
        }
    }
}

// Final WO projection: fp32 output.
__global__ void __launch_bounds__(256, 2) gemm_out_kernel(
    const __nv_bfloat16* __restrict__ Ah, const __nv_bfloat16* __restrict__ Al,
    const __nv_bfloat16* __restrict__ Bh, const __nv_bfloat16* __restrict__ Bl,
    float* __restrict__ C)
{
    extern __shared__ char smem[];
    const uint32_t sb = s2u(smem);
    const int tid = threadIdx.x;
    const int wid = tid >> 5, l = tid & 31;
    const int bn = blockIdx.x, bm = blockIdx.y;

    const __nv_bfloat16* Ahb = Ah + (size_t)bm * 128 * EMB;
    const __nv_bfloat16* Alb = Al + (size_t)bm * 128 * EMB;
    const __nv_bfloat16* Bhb = Bh + (size_t)bn * 128 * EMB;
    const __nv_bfloat16* Blb = Bl + (size_t)bn * 128 * EMB;

    float acc[2][8][4];
    gemm_mainloop(sb, tid, Ahb, Alb, Bhb, Blb, acc);

    const int wm = wid & 3, wn = wid >> 2;
    const int g = l >> 2, t2 = (l & 3) * 2;
    #pragma unroll
    for (int mi = 0; mi < 2; mi++) {
        #pragma unroll
        for (int ni = 0; ni < 8; ni++) {
            const int row = bm * 128 + wm * 32 + mi * 16 + g;
            const int col = bn * 128 + wn * 64 + ni * 8 + t2;
            const size_t o0 = (size_t)row * EMB + col;
            const size_t o1 = o0 + (size_t)8 * EMB;
            *(float2*)(C + o0) = make_float2(acc[mi][ni][0], acc[mi][ni][1]);
            *(float2*)(C + o1) = make_float2(acc[mi][ni][2], acc[mi][ni][3]);
        }
    }
}

// ---------------------------------------------------------------------------
// HMMA causal flash attention. BR=128 (8 warps, 256 threads), BC=64, dk=64.
// Warp w owns q rows w*16..w*16+15 of the 128-row block. Q fragments loaded
// directly from global. K/V hi/lo double-buffered via cp.async.
// Per-warp diagonal block kb_diag = 2qb + (w>=4); later blocks skipped.
// 2 CTAs/SM (16 warps). Heavy CTAs launch first (qb reversed).
// ---------------------------------------------------------------------------
#define FSTR  144
#define FTILE (64 * FSTR)        // 9216
#define FKVSZ (4 * FTILE)        // 36864 (Kh, Kl, Vh, Vl)
#define FSMEM (2 * FKVSZ)        // 73728

__device__ __forceinline__ void flash_loadKV(uint32_t base,
    const __nv_bfloat16* kh, const __nv_bfloat16* kl,
    const __nv_bfloat16* vh, const __nv_bfloat16* vl,
    size_t rowK, int col0, int kb, int tid)
{
    const __nv_bfloat16* srcs[4] = { kh, kl, vh, vl };
    #pragma unroll
    for (int i = 0; i < 8; i++) {
        int idx = tid + i * 256;       // 0..2047
        int tile = idx >> 9;           // 0..3
        int r = (idx >> 3) & 63;
        int c16 = (idx & 7) * 16;
        cpasync16(base + tile * FTILE + r * FSTR + c16,
                  (const char*)(srcs[tile] + (rowK + kb * 64 + r) * EMB + col0) + c16);
    }
    CP_COMMIT();
}

__global__ void __launch_bounds__(256, 2) flash_hmma_kernel(
    const __nv_bfloat16* __restrict__ qh, const __nv_bfloat16* __restrict__ ql,
    const __nv_bfloat16* __restrict__ kh, const __nv_bfloat16* __restrict__ kl,
    const __nv_bfloat16* __restrict__ vh, const __nv_bfloat16* __restrict__ vl,
    __nv_bfloat16* __restrict__ ah, __nv_bfloat16* __restrict__ al)
{
    extern __shared__ char fsm[];
    const uint32_t sb = s2u(fsm);
    const int tid = threadIdx.x;
    const int wid = tid >> 5, l = tid & 31;
    const int qb = (int)(gridDim.x - 1 - blockIdx.x);   // heavy CTAs first
    const int h = blockIdx.y, b = blockIdx.z;
    const int g = l >> 2, t = l & 3;

    const size_t rowQ = (size_t)(b * SEQ + qb * 128);
    const size_t rowK = (size_t)(b * SEQ);
    const int col0 = h * DK;

    // Kick off K/V stage 0 first so Q loads overlap the cp.async flight
    flash_loadKV(sb, kh, kl, vh, vl, rowK, col0, 0, tid);

    // Q fragments (A of m16n8k16) straight from global:
    // a0:(g,2t) a1:(g+8,2t) a2:(g,2t+8) a3:(g+8,2t+8) per k16 block kt
    uint32_t qhf[4][4], qlf[4][4];
    {
        const __nv_bfloat16* qrh = qh + (rowQ + wid * 16) * EMB + col0;
        const __nv_bfloat16* qrl = ql + (rowQ + wid * 16) * EMB + col0;
        #pragma unroll
        for (int kt = 0; kt < 4; kt++) {
            const int cb = kt * 16 + 2 * t;
            qhf[kt][0] = *(const uint32_t*)(qrh + (size_t)g * EMB + cb);
            qhf[kt][1] = *(const uint32_t*)(qrh + (size_t)(g + 8) * EMB + cb);
            qhf[kt][2] = *(const uint32_t*)(qrh + (size_t)g * EMB + cb + 8);
            qhf[kt][3] = *(const uint32_t*)(qrh + (size_t)(g + 8) * EMB + cb + 8);
            qlf[kt][0] = *(const uint32_t*)(qrl + (size_t)g * EMB + cb);
            qlf[kt][1] = *(const uint32_t*)(qrl + (size_t)(g + 8) * EMB + cb);
            qlf[kt][2] = *(const uint32_t*)(qrl + (size_t)g * EMB + cb + 8);
            qlf[kt][3] = *(const uint32_t*)(qrl + (size_t)(g + 8) * EMB + cb + 8);
        }
    }

    float o[8][4];
    #pragma unroll
    for (int j = 0; j < 8; j++)
        #pragma unroll
        for (int r = 0; r < 4; r++) o[j][r] = 0.f;
    float m0 = NEG_INF, m1 = NEG_INF, sl0 = 0.f, sl1 = 0.f;
    // global query rows of this warp's two 8-row groups
    const int lr0 = qb * 128 + wid * 16 + g, lr1 = lr0 + 8;
    // per-warp diagonal kv-block; blocks beyond are entirely future
    const int kb_diag = 2 * qb + (wid >> 2);

    const int nkb = 2 * qb + 2;
    for (int kb = 0; kb < nkb; kb++) {
        if (kb + 1 < nkb) {
            flash_loadKV(sb + ((kb + 1) & 1) * FKVSZ,
                         kh, kl, vh, vl, rowK, col0, kb + 1, tid);
            asm volatile("cp.async.wait_group 1;" ::: "memory");
        } else {
            asm volatile("cp.async.wait_group 0;" ::: "memory");
        }
        __syncthreads();

        if (kb <= kb_diag) {
            const uint32_t Kb = sb + (kb & 1) * FKVSZ;

            // S = Q K^T (split)
            float s[8][4];
            #pragma unroll
            for (int j = 0; j < 8; j++)
                #pragma unroll
                for (int r = 0; r < 4; r++) s[j][r] = 0.f;

            #pragma unroll
            for (int kt = 0; kt < 4; kt++) {
                #pragma unroll
                for (int p = 0; p < 4; p++) {
                    uint32_t kboff = (uint32_t)((p * 16 + (l & 7) + ((l >> 4) << 3)) * FSTR
                                                + ((l >> 3) & 1) * 16 + kt * 32);
                    uint32_t khb[4], klb[4];
                    ldx4(khb, Kb + kboff);
                    ldx4(klb, Kb + FTILE + kboff);
                    #pragma unroll
                    for (int sub = 0; sub < 2; sub++) {
                        float* d = s[p * 2 + sub];
                        const uint32_t b0 = khb[sub * 2], b1 = khb[sub * 2 + 1];
                        mma_bf16(d, qhf[kt], b0, b1);
                        mma_bf16(d, qhf[kt], klb[sub * 2], klb[sub * 2 + 1]);
                        mma_bf16(d, qlf[kt], b0, b1);
                    }
                }
            }

            // causal mask on diagonal block (raw scores; CS > 0 commutes)
            if (kb == kb_diag) {
                #pragma unroll
                for (int j = 0; j < 8; j++) {
                    const int c0 = kb * 64 + j * 8 + t * 2, c1 = c0 + 1;
                    if (c0 > lr0) s[j][0] = NEG_INF;
                    if (c1 > lr0) s[j][1] = NEG_INF;
                    if (c0 > lr1) s[j][2] = NEG_INF;
                    if (c1 > lr1) s[j][3] = NEG_INF;
                }
            }

            // online softmax; CS = 0.125*log2(e) folded into the ex2 FFMA
            const float CS = 0.18033688011112042f;
            float rm0 = NEG_INF, rm1 = NEG_INF;
            #pragma unroll
            for (int j = 0; j < 8; j++) {
                rm0 = fmaxf(rm0, fmaxf(s[j][0], s[j][1]));
                rm1 = fmaxf(rm1, fmaxf(s[j][2], s[j][3]));
            }
            rm0 = fmaxf(rm0, __shfl_xor_sync(0xffffffffu, rm0, 1));
            rm0 = fmaxf(rm0, __shfl_xor_sync(0xffffffffu, rm0, 2));
            rm1 = fmaxf(rm1, __shfl_xor_sync(0xffffffffu, rm1, 1));
            rm1 = fmaxf(rm1, __shfl_xor_sync(0xffffffffu, rm1, 2));
            rm0 *= CS;                       // scale AFTER reduction
            rm1 *= CS;

            const float mn0 = fmaxf(m0, rm0), mn1 = fmaxf(m1, rm1);
            const float al0 = ex2f(m0 - mn0), al1 = ex2f(m1 - mn1);
            m0 = mn0; m1 = mn1;

            float sum0 = 0.f, sum1 = 0.f;
            #pragma unroll
            for (int j = 0; j < 8; j++) {
                s[j][0] = ex2f(fmaf(s[j][0], CS, -mn0));
                s[j][1] = ex2f(fmaf(s[j][1], CS, -mn0));
                s[j][2] = ex2f(fmaf(s[j][2], CS, -mn1));
                s[j][3] = ex2f(fmaf(s[j][3], CS, -mn1));
                sum0 += s[j][0] + s[j][1];
                sum1 += s[j][2] + s[j][3];
            }
            sum0 += __shfl_xor_sync(0xffffffffu, sum0, 1);
            sum0 += __shfl_xor_sync(0xffffffffu, sum0, 2);
            sum1 += __shfl_xor_sync(0xffffffffu, sum1, 1);
            sum1 += __shfl_xor_sync(0xffffffffu, sum1, 2);
            sl0 = sl0 * al0 + sum0;
            sl1 = sl1 * al1 + sum1;

            #pragma unroll
            for (int j = 0; j < 8; j++) {
                o[j][0] *= al0; o[j][1] *= al0;
                o[j][2] *= al1; o[j][3] *= al1;
            }

            // O += P V (P repacked from S fragments, split hi/lo; V^T via ldmatrix.trans)
            #pragma unroll
            for (int kt = 0; kt < 4; kt++) {
                uint32_t phf[4], plf[4];
                {
                    const int j0 = 2 * kt, j1 = 2 * kt + 1;
                    phf[0] = packbf(s[j0][0], s[j0][1]);
                    phf[1] = packbf(s[j0][2], s[j0][3]);
                    phf[2] = packbf(s[j1][0], s[j1][1]);
                    phf[3] = packbf(s[j1][2], s[j1][3]);
                    plf[0] = packbf(s[j0][0] - bfloat_lo(phf[0]), s[j0][1] - bfloat_hi(phf[0]));
                    plf[1] = packbf(s[j0][2] - bfloat_lo(phf[1]), s[j0][3] - bfloat_hi(phf[1]));
                    plf[2] = packbf(s[j1][0] - bfloat_lo(phf[2]), s[j1][1] - bfloat_hi(phf[2]));
                    plf[3] = packbf(s[j1][2] - bfloat_lo(phf[3]), s[j1][3] - bfloat_hi(phf[3]));
                }
                #pragma unroll
                for (int p = 0; p < 4; p++) {
                    uint32_t voff = (uint32_t)((kt * 16 + ((l >> 3) & 1) * 8 + (l & 7)) * FSTR
                                               + p * 32 + ((l >> 4) << 4));
                    uint32_t vhb[4], vlb[4];
                    ldx4t(vhb, Kb + 2 * FTILE + voff);
                    ldx4t(vlb, Kb + 3 * FTILE + voff);
                    #pragma unroll
                    for (int sub = 0; sub < 2; sub++) {
                        float* d = o[p * 2 + sub];
                        const uint32_t b0 = vhb[sub * 2], b1 = vhb[sub * 2 + 1];
                        mma_bf16(d, phf, b0, b1);
                        mma_bf16(d, phf, vlb[sub * 2], vlb[sub * 2 + 1]);
                        mma_bf16(d, plf, b0, b1);
                    }
                }
            }
        }
        __syncthreads();
    }

    // Epilogue: normalize, split to bf16 hi/lo, store
    const float inv0 = 1.f / sl0, inv1 = 1.f / sl1;
    const size_t r0o = ((size_t)(b * SEQ) + lr0) * EMB + col0;
    const size_t r1o = ((size_t)(b * SEQ) + lr1) * EMB + col0;
    #pragma unroll
    for (int j = 0; j < 8; j++) {
        const int c = j * 8 + t * 2;
        float v0 = o[j][0] * inv0, v1 = o[j][1] * inv0;
        float v2 = o[j][2] * inv1, v3 = o[j][3] * inv1;
        uint32_t h0 = packbf(v0, v1);
        uint32_t l0 = packbf(v0 - bfloat_lo(h0), v1 - bfloat_hi(h0));
        uint32_t h1 = packbf(v2, v3);
        uint32_t l1 = packbf(v2 - bfloat_lo(h1), v3 - bfloat_hi(h1));
        *(uint32_t*)(ah + r0o + c) = h0;
        *(uint32_t*)(al + r0o + c) = l0;
        *(uint32_t*)(ah + r1o + c) = h1;
        *(uint32_t*)(al + r1o + c) = l1;
    }
}

// ---------------------------------------------------------------------------
// Launch
// ---------------------------------------------------------------------------
extern "C" void kernel_launch(void* const* d_in, const int* in_sizes, int n_in,
                              void* d_out, int out_size)
{
    const float* x  = (const float*)d_in[0];
    const float* W[4] = { (const float*)d_in[1], (const float*)d_in[2],
                          (const float*)d_in[3], (const float*)d_in[4] };
    float* out = (float*)d_out;

    void *pQ, *pK, *pV, *pxh, *pxl, *pah, *pal, *pwh, *pwl;
    cudaGetSymbolAddress(&pQ, g_Qp);
    cudaGetSymbolAddress(&pK, g_Kp);
    cudaGetSymbolAddress(&pV, g_Vp);
    cudaGetSymbolAddress(&pxh, g_xh);
    cudaGetSymbolAddress(&pxl, g_xl);
    cudaGetSymbolAddress(&pah, g_ah);
    cudaGetSymbolAddress(&pal, g_al);
    cudaGetSymbolAddress(&pwh, g_wh);
    cudaGetSymbolAddress(&pwl, g_wl);

    cudaFuncSetAttribute(gemm_qkv_kernel,
                         cudaFuncAttributeMaxDynamicSharedMemorySize, GEMM_SMEM);
    cudaFuncSetAttribute(gemm_out_kernel,
                         cudaFuncAttributeMaxDynamicSharedMemorySize, GEMM_SMEM);
    cudaFuncSetAttribute(flash_hmma_kernel,
                         cudaFuncAttributeMaxDynamicSharedMemorySize, FSMEM);

    __nv_bfloat16* xh = (__nv_bfloat16*)pxh;
    __nv_bfloat16* xl = (__nv_bfloat16*)pxl;
    __nv_bfloat16* ah = (__nv_bfloat16*)pah;
    __nv_bfloat16* al = (__nv_bfloat16*)pal;
    __nv_bfloat16* wh = (__nv_bfloat16*)pwh;
    __nv_bfloat16* wl = (__nv_bfloat16*)pwl;

    // fp32 scratch aliased as (hi, lo) bf16 pairs
    __nv_bfloat16* qhp = (__nv_bfloat16*)pQ; __nv_bfloat16* qlp = qhp + NELEM;
    __nv_bfloat16* khp = (__nv_bfloat16*)pK; __nv_bfloat16* klp = khp + NELEM;
    __nv_bfloat16* vhp = (__nv_bfloat16*)pV; __nv_bfloat16* vlp = vhp + NELEM;

    // 1) split x into bf16 hi/lo
    split_kernel<<<NELEM / 4 / 256, 256>>>(x, xh, xl, NELEM);

    // 2) transpose+split the four weight matrices
    dim3 wGrid(EMB / 32, EMB / 32), wBlk(32, 8);
    for (int i = 0; i < 4; i++)
        wsplit_kernel<<<wGrid, wBlk>>>(W[i], wh + (size_t)i * EMB * EMB,
                                       wl + (size_t)i * EMB * EMB);

    // 3) fused Q/K/V projections -> bf16 hi/lo directly
    dim3 gGrid(3 * EMB / 128, MROWS / 128);   // (24, 64)
    gemm_qkv_kernel<<<gGrid, 256, GEMM_SMEM>>>(
        xh, xl, wh, wl, qhp, qlp, khp, klp, vhp, vlp);

    // 4) causal flash attention on HMMA (BR=128) -> split ah/al directly
    dim3 fGrid(SEQ / 128, HEADS, BATCH);   // (16, 16, 4)
    flash_hmma_kernel<<<fGrid, 256, FSMEM>>>(qhp, qlp, khp, klp, vhp, vlp, ah, al);

    // 5) final projection (fp32 out)
    dim3 oGrid(EMB / 128, MROWS / 128);   // (8, 64)
    gemm_out_kernel<<<oGrid, 256, GEMM_SMEM>>>(
        ah, al, wh + 3 * (size_t)EMB * EMB, wl + 3 * (size_t)EMB * EMB, out);
}

// round 16
// speedup vs baseline: 1.1514x; 1.1514x over previous
#include <cuda_runtime.h>
#include <cuda_bf16.h>
#include <cuda_fp16.h>
#include <math.h>
#include <stdint.h>

// Problem constants
#define BATCH 4
#define SEQ   2048
#define EMB   1024
#define HEADS 16
#define DK    64
#define MROWS (BATCH*SEQ)   // 8192
#define NELEM (MROWS*EMB)

// ---------------------------------------------------------------------------
// Scratch (static device arrays; no allocations allowed).
// g_Qp/g_Kp (fp32-sized) aliased as PAIRS of bf16 arrays (hi, lo).
// g_Vp holds V as fp16 single (half the array used).
// ---------------------------------------------------------------------------
__device__ float g_Qp[NELEM];
__device__ float g_Kp[NELEM];
__device__ float g_Vp[NELEM];

__device__ __nv_bfloat16 g_xh[NELEM];   // x split hi
__device__ __nv_bfloat16 g_xl[NELEM];   // x split lo
__device__ __nv_bfloat16 g_ah[NELEM];   // attn out split hi
__device__ __nv_bfloat16 g_al[NELEM];   // attn out split lo
__device__ __nv_bfloat16 g_wh[4][EMB * EMB];  // W^T split hi  [n][k]
__device__ __nv_bfloat16 g_wl[4][EMB * EMB];  // W^T split lo  [n][k]

// ---------------------------------------------------------------------------
// PTX helpers (sm_80-era only; legal on plain sm_103 PTX target)
// ---------------------------------------------------------------------------
__device__ __forceinline__ uint32_t s2u(const void* p) {
    uint32_t a;
    asm("{ .reg .u64 t; cvta.to.shared.u64 t, %1; cvt.u32.u64 %0, t; }"
        : "=r"(a) : "l"(p));
    return a;
}

__device__ __forceinline__ void cpasync16(uint32_t dst, const void* src) {
    asm volatile("cp.async.cg.shared.global [%0], [%1], 16;"
                 :: "r"(dst), "l"(src));
}
#define CP_COMMIT() asm volatile("cp.async.commit_group;" ::: "memory")

__device__ __forceinline__ void ldx4(uint32_t* r, uint32_t addr) {
    asm volatile("ldmatrix.sync.aligned.m8n8.x4.shared.b16 {%0,%1,%2,%3}, [%4];"
                 : "=r"(r[0]), "=r"(r[1]), "=r"(r[2]), "=r"(r[3])
                 : "r"(addr));
}

__device__ __forceinline__ void ldx4t(uint32_t* r, uint32_t addr) {
    asm volatile("ldmatrix.sync.aligned.m8n8.x4.trans.shared.b16 {%0,%1,%2,%3}, [%4];"
                 : "=r"(r[0]), "=r"(r[1]), "=r"(r[2]), "=r"(r[3])
                 : "r"(addr));
}

__device__ __forceinline__ void mma_bf16(float* d, const uint32_t* a,
                                         uint32_t b0, uint32_t b1) {
    asm volatile("mma.sync.aligned.m16n8k16.row.col.f32.bf16.bf16.f32 "
                 "{%0,%1,%2,%3}, {%4,%5,%6,%7}, {%8,%9}, {%0,%1,%2,%3};"
                 : "+f"(d[0]), "+f"(d[1]), "+f"(d[2]), "+f"(d[3])
                 : "r"(a[0]), "r"(a[1]), "r"(a[2]), "r"(a[3]),
                   "r"(b0), "r"(b1));
}

__device__ __forceinline__ void mma_f16(float* d, const uint32_t* a,
                                        uint32_t b0, uint32_t b1) {
    asm volatile("mma.sync.aligned.m16n8k16.row.col.f32.f16.f16.f32 "
                 "{%0,%1,%2,%3}, {%4,%5,%6,%7}, {%8,%9}, {%0,%1,%2,%3};"
                 : "+f"(d[0]), "+f"(d[1]), "+f"(d[2]), "+f"(d[3])
                 : "r"(a[0]), "r"(a[1]), "r"(a[2]), "r"(a[3]),
                   "r"(b0), "r"(b1));
}

// pack two fp32 into bf16x2 (lo = first element, little-endian low half)
__device__ __forceinline__ uint32_t packbf(float lo, float hi) {
    uint32_t r;
    asm("cvt.rn.bf16x2.f32 %0, %1, %2;" : "=r"(r) : "f"(hi), "f"(lo));
    return r;
}
// pack two fp32 into f16x2
__device__ __forceinline__ uint32_t packhf(float lo, float hi) {
    uint32_t r;
    asm("cvt.rn.f16x2.f32 %0, %1, %2;" : "=r"(r) : "f"(hi), "f"(lo));
    return r;
}
// bf16x2 halves back to fp32 (exact: bf16 -> fp32 is a 16-bit shift)
__device__ __forceinline__ float bfloat_lo(uint32_t p) { return __uint_as_float(p << 16); }
__device__ __forceinline__ float bfloat_hi(uint32_t p) { return __uint_as_float(p & 0xffff0000u); }

__device__ __forceinline__ float ex2f(float x) {
    float y;
    asm("ex2.approx.ftz.f32 %0, %1;" : "=f"(y) : "f"(x));
    return y;
}

#define NEG_INF __int_as_float(0xff800000)

// ---------------------------------------------------------------------------
// Split kernel: fp32 -> (bf16 hi, bf16 lo residual)
// ---------------------------------------------------------------------------
__global__ void split_kernel(const float* __restrict__ in,
                             __nv_bfloat16* __restrict__ hi,
                             __nv_bfloat16* __restrict__ lo, int n)
{
    int i = (blockIdx.x * blockDim.x + threadIdx.x) * 4;
    if (i >= n) return;
    float4 v = *(const float4*)(in + i);
    uint32_t h01 = packbf(v.x, v.y);
    uint32_t h23 = packbf(v.z, v.w);
    uint32_t l01 = packbf(v.x - bfloat_lo(h01), v.y - bfloat_hi(h01));
    uint32_t l23 = packbf(v.z - bfloat_lo(h23), v.w - bfloat_hi(h23));
    *(uint32_t*)(hi + i)     = h01;
    *(uint32_t*)(hi + i + 2) = h23;
    *(uint32_t*)(lo + i)     = l01;
    *(uint32_t*)(lo + i + 2) = l23;
}

// ---------------------------------------------------------------------------
// Weight transpose + split: Wt[n][k] = split(W[k][n]), 32x32 smem tiles
// ---------------------------------------------------------------------------
__global__ void wsplit_kernel(const float* __restrict__ W,
                              __nv_bfloat16* __restrict__ ht,
                              __nv_bfloat16* __restrict__ lt)
{
    __shared__ float t[32][33];
    const int tx = threadIdx.x, ty = threadIdx.y;      // 32 x 8
    const int n0 = blockIdx.x * 32, k0 = blockIdx.y * 32;
    #pragma unroll
    for (int j = 0; j < 4; j++)
        t[ty + 8 * j][tx] = W[(size_t)(k0 + ty + 8 * j) * EMB + n0 + tx];
    __syncthreads();
    #pragma unroll
    for (int j = 0; j < 4; j++) {
        float v = t[tx][ty + 8 * j];
        __nv_bfloat16 h = __float2bfloat16(v);
        __nv_bfloat16 l = __float2bfloat16(v - __bfloat162float(h));
        size_t o = (size_t)(n0 + ty + 8 * j) * EMB + k0 + tx;
        ht[o] = h;
        lt[o] = l;
    }
}

// ---------------------------------------------------------------------------
// HMMA split-bf16 GEMM core (CTA tile 128x128, BK=32, 2-stage cp.async).
// ---------------------------------------------------------------------------
#define GBK       32
#define NCHUNK    (EMB / GBK)          // 32
#define TILE_B    (128 * 80)           // 10240 B per operand tile
#define STAGE_B   (4 * TILE_B)         // Ah, Al, Bh, Bl = 40960 B
#define GEMM_SMEM (2 * STAGE_B)        // 81920 B

__device__ __forceinline__ void load_chunk(uint32_t st,
    const __nv_bfloat16* Ah, const __nv_bfloat16* Al,
    const __nv_bfloat16* Bh, const __nv_bfloat16* Bl,
    int k0, int tid)
{
    const __nv_bfloat16* srcs[4] = { Ah, Al, Bh, Bl };
    #pragma unroll
    for (int t = 0; t < 4; t++) {
        const char* base = (const char*)srcs[t] + (size_t)k0 * 2;
        #pragma unroll
        for (int j = 0; j < 2; j++) {
            int idx = tid + j * 256;       // 0..511
            int row = idx >> 2;            // 0..127
            int c16 = (idx & 3) * 16;      // 0,16,32,48
            cpasync16(st + t * TILE_B + row * 80 + c16,
                      base + (size_t)row * (EMB * 2) + c16);
        }
    }
}

// Mainloop: computes acc[2][8][4] for tile (bm, bn) of A * B.
__device__ __forceinline__ void gemm_mainloop(
    uint32_t sb, int tid,
    const __nv_bfloat16* Ahb, const __nv_bfloat16* Alb,
    const __nv_bfloat16* Bhb, const __nv_bfloat16* Blb,
    float acc[2][8][4])
{
    const int wid = tid >> 5, l = tid & 31;
    const int wm = wid & 3;
    const int wn = wid >> 2;

    int aoffm[2];
    #pragma unroll
    for (int mi = 0; mi < 2; mi++)
        aoffm[mi] = (wm * 32 + mi * 16 + (l & 15)) * 80 + ((l >> 4) & 1) * 16;
    int boffp[4];
    #pragma unroll
    for (int p = 0; p < 4; p++)
        boffp[p] = (wn * 64 + p * 16 + (l & 7) + ((l >> 4) << 3)) * 80
                 + ((l >> 3) & 1) * 16;

    #pragma unroll
    for (int mi = 0; mi < 2; mi++)
        #pragma unroll
        for (int ni = 0; ni < 8; ni++)
            #pragma unroll
            for (int r = 0; r < 4; r++) acc[mi][ni][r] = 0.f;

    load_chunk(sb + 0 * STAGE_B, Ahb, Alb, Bhb, Blb, 0 * GBK, tid);
    CP_COMMIT();
    load_chunk(sb + 1 * STAGE_B, Ahb, Alb, Bhb, Blb, 1 * GBK, tid);
    CP_COMMIT();

    for (int c = 0; c < NCHUNK; c++) {
        if (c < NCHUNK - 1) asm volatile("cp.async.wait_group 1;" ::: "memory");
        else                asm volatile("cp.async.wait_group 0;" ::: "memory");
        __syncthreads();

        const uint32_t st = sb + (c & 1) * STAGE_B;
        #pragma unroll
        for (int ks = 0; ks < 2; ks++) {
            const uint32_t koff = ks * 32;
            uint32_t ah[2][4], al[2][4];
            #pragma unroll
            for (int mi = 0; mi < 2; mi++) {
                ldx4(ah[mi], st + 0 * TILE_B + aoffm[mi] + koff);
                ldx4(al[mi], st + 1 * TILE_B + aoffm[mi] + koff);
            }
            #pragma unroll
            for (int p = 0; p < 4; p++) {
                uint32_t bh[4], bl[4];
                ldx4(bh, st + 2 * TILE_B + boffp[p] + koff);
                ldx4(bl, st + 3 * TILE_B + boffp[p] + koff);
                #pragma unroll
                for (int mi = 0; mi < 2; mi++) {
                    #pragma unroll
                    for (int sub = 0; sub < 2; sub++) {
                        float* d = acc[mi][p * 2 + sub];
                        const uint32_t b0 = bh[sub * 2], b1 = bh[sub * 2 + 1];
                        mma_bf16(d, ah[mi], b0, b1);
                        mma_bf16(d, ah[mi], bl[sub * 2], bl[sub * 2 + 1]);
                        mma_bf16(d, al[mi], b0, b1);
                    }
                }
            }
        }
        __syncthreads();

        if (c + 2 < NCHUNK) {
            load_chunk(st, Ahb, Alb, Bhb, Blb, (c + 2) * GBK, tid);
            CP_COMMIT();
        }
    }
}

// Fused Q/K/V projection: grid (24, 64); bn>>3 selects weight + output.
// Q,K outputs: bf16 hi/lo split. V output (widx==2): fp16 single.
__global__ void __launch_bounds__(256, 2) gemm_qkv_kernel(
    const __nv_bfloat16* __restrict__ Ah, const __nv_bfloat16* __restrict__ Al,
    const __nv_bfloat16* __restrict__ Wh, const __nv_bfloat16* __restrict__ Wl,
    __nv_bfloat16* __restrict__ q_h, __nv_bfloat16* __restrict__ q_l,
    __nv_bfloat16* __restrict__ k_h, __nv_bfloat16* __restrict__ k_l,
    __half* __restrict__ v_f)
{
    extern __shared__ char smem[];
    const uint32_t sb = s2u(smem);
    const int tid = threadIdx.x;
    const int wid = tid >> 5, l = tid & 31;
    const int bnf = blockIdx.x, bm = blockIdx.y;
    const int widx = bnf >> 3, bn = bnf & 7;

    const __nv_bfloat16* Ahb = Ah + (size_t)bm * 128 * EMB;
    const __nv_bfloat16* Alb = Al + (size_t)bm * 128 * EMB;
    const __nv_bfloat16* Bhb = Wh + (size_t)widx * EMB * EMB + (size_t)bn * 128 * EMB;
    const __nv_bfloat16* Blb = Wl + (size_t)widx * EMB * EMB + (size_t)bn * 128 * EMB;

    float acc[2][8][4];
    gemm_mainloop(sb, tid, Ahb, Alb, Bhb, Blb, acc);

    const int wm = wid & 3, wn = wid >> 2;
    const int g = l >> 2, t2 = (l & 3) * 2;
    __nv_bfloat16* Ch = (widx == 0) ? q_h : k_h;
    __nv_bfloat16* Cl = (widx == 0) ? q_l : k_l;
    #pragma unroll
    for (int mi = 0; mi < 2; mi++) {
        #pragma unroll
        for (int ni = 0; ni < 8; ni++) {
            const int row = bm * 128 + wm * 32 + mi * 16 + g;
            const int col = bn * 128 + wn * 64 + ni * 8 + t2;
            const size_t o0 = (size_t)row * EMB + col;
            const size_t o1 = o0 + (size_t)8 * EMB;
            if (widx == 2) {
                *(uint32_t*)(v_f + o0) = packhf(acc[mi][ni][0], acc[mi][ni][1]);
                *(uint32_t*)(v_f + o1) = packhf(acc[mi][ni][2], acc[mi][ni][3]);
            } else {
                uint32_t h0 = packbf(acc[mi][ni][0], acc[mi][ni][1]);
                uint32_t l0 = packbf(acc[mi][ni][0] - bfloat_lo(h0),
                                     acc[mi][ni][1] - bfloat_hi(h0));
                uint32_t h1 = packbf(acc[mi][ni][2], acc[mi][ni][3]);
                uint32_t l1 = packbf(acc[mi][ni][2] - bfloat_lo(h1),
                                     acc[mi][ni][3] - bfloat_hi(h1));
                *(uint32_t*)(Ch + o0) = h0;
                *(uint32_t*)(Cl + o0) = l0;
                *(uint32_t*)(Ch + o1) = h1;
                *(uint32_t*)(Cl + o1) = l1;
            }
        }
    }
}

// Final WO projection: fp32 output.
__global__ void __launch_bounds__(256, 2) gemm_out_kernel(
    const __nv_bfloat16* __restrict__ Ah, const __nv_bfloat16* __restrict__ Al,
    const __nv_bfloat16* __restrict__ Bh, const __nv_bfloat16* __restrict__ Bl,
    float* __restrict__ C)
{
    extern __shared__ char smem[];
    const uint32_t sb = s2u(smem);
    const int tid = threadIdx.x;
    const int wid = tid >> 5, l = tid & 31;
    const int bn = blockIdx.x, bm = blockIdx.y;

    const __nv_bfloat16* Ahb = Ah + (size_t)bm * 128 * EMB;
    const __nv_bfloat16* Alb = Al + (size_t)bm * 128 * EMB;
    const __nv_bfloat16* Bhb = Bh + (size_t)bn * 128 * EMB;
    const __nv_bfloat16* Blb = Bl + (size_t)bn * 128 * EMB;

    float acc[2][8][4];
    gemm_mainloop(sb, tid, Ahb, Alb, Bhb, Blb, acc);

    const int wm = wid & 3, wn = wid >> 2;
    const int g = l >> 2, t2 = (l & 3) * 2;
    #pragma unroll
    for (int mi = 0; mi < 2; mi++) {
        #pragma unroll
        for (int ni = 0; ni < 8; ni++) {
            const int row = bm * 128 + wm * 32 + mi * 16 + g;
            const int col = bn * 128 + wn * 64 + ni * 8 + t2;
            const size_t o0 = (size_t)row * EMB + col;
            const size_t o1 = o0 + (size_t)8 * EMB;
            *(float2*)(C + o0) = make_float2(acc[mi][ni][0], acc[mi][ni][1]);
            *(float2*)(C + o1) = make_float2(acc[mi][ni][2], acc[mi][ni][3]);
        }
    }
}

// ---------------------------------------------------------------------------
// HMMA causal flash attention. BR=64, BC=64, dk=64, 4 warps (128 threads),
// 3 CTAs/SM. QK^T: 3-product split-bf16. P.V: SINGLE fp16 product (P and V
// both fp16). Q fragments direct from global; K(hi/lo) + V(fp16) staged in
// smem, double-buffered via cp.async. Heavy CTAs launch first.
// ---------------------------------------------------------------------------
#define FSTR  144
#define FTILE (64 * FSTR)        // 9216
#define FKVSZ (3 * FTILE)        // 27648 (Kh, Kl, Vf)
#define FSMEM (2 * FKVSZ)        // 55296

__device__ __forceinline__ void flash_loadKV(uint32_t base,
    const __nv_bfloat16* kh, const __nv_bfloat16* kl, const __half* vf,
    size_t rowK, int col0, int kb, int tid)
{
    const void* srcs[3] = { kh, kl, vf };
    #pragma unroll
    for (int i = 0; i < 12; i++) {
        int idx = tid + i * 128;       // 0..1535
        int tile = idx >> 9;           // 0..2
        int r = (idx >> 3) & 63;
        int c16 = (idx & 7) * 16;
        cpasync16(base + tile * FTILE + r * FSTR + c16,
                  (const char*)srcs[tile]
                  + ((rowK + kb * 64 + r) * EMB + col0) * 2 + c16);
    }
    CP_COMMIT();
}

__global__ void __launch_bounds__(128, 3) flash_hmma_kernel(
    const __nv_bfloat16* __restrict__ qh, const __nv_bfloat16* __restrict__ ql,
    const __nv_bfloat16* __restrict__ kh, const __nv_bfloat16* __restrict__ kl,
    const __half* __restrict__ vf,
    __nv_bfloat16* __restrict__ ah, __nv_bfloat16* __restrict__ al)
{
    extern __shared__ char fsm[];
    const uint32_t sb = s2u(fsm);
    const int tid = threadIdx.x;
    const int wid = tid >> 5, l = tid & 31;
    const int qb = (int)(gridDim.x - 1 - blockIdx.x);   // heavy CTAs first
    const int h = blockIdx.y, b = blockIdx.z;
    const int g = l >> 2, t = l & 3;

    const size_t rowQ = (size_t)(b * SEQ + qb * 64);
    const size_t rowK = (size_t)(b * SEQ);
    const int col0 = h * DK;

    // Kick off K/V stage 0 first so Q loads overlap the cp.async flight
    flash_loadKV(sb, kh, kl, vf, rowK, col0, 0, tid);

    // Q fragments (A of m16n8k16) straight from global:
    // a0:(g,2t) a1:(g+8,2t) a2:(g,2t+8) a3:(g+8,2t+8) per k16 block kt
    uint32_t qhf[4][4], qlf[4][4];
    {
        const __nv_bfloat16* qrh = qh + (rowQ + wid * 16) * EMB + col0;
        const __nv_bfloat16* qrl = ql + (rowQ + wid * 16) * EMB + col0;
        #pragma unroll
        for (int kt = 0; kt < 4; kt++) {
            const int cb = kt * 16 + 2 * t;
            qhf[kt][0] = *(const uint32_t*)(qrh + (size_t)g * EMB + cb);
            qhf[kt][1] = *(const uint32_t*)(qrh + (size_t)(g + 8) * EMB + cb);
            qhf[kt][2] = *(const uint32_t*)(qrh + (size_t)g * EMB + cb + 8);
            qhf[kt][3] = *(const uint32_t*)(qrh + (size_t)(g + 8) * EMB + cb + 8);
            qlf[kt][0] = *(const uint32_t*)(qrl + (size_t)g * EMB + cb);
            qlf[kt][1] = *(const uint32_t*)(qrl + (size_t)(g + 8) * EMB + cb);
            qlf[kt][2] = *(const uint32_t*)(qrl + (size_t)g * EMB + cb + 8);
            qlf[kt][3] = *(const uint32_t*)(qrl + (size_t)(g + 8) * EMB + cb + 8);
        }
    }

    float o[8][4];
    #pragma unroll
    for (int j = 0; j < 8; j++)
        #pragma unroll
        for (int r = 0; r < 4; r++) o[j][r] = 0.f;
    float m0 = NEG_INF, m1 = NEG_INF, sl0 = 0.f, sl1 = 0.f;
    const int lr0 = wid * 16 + g, lr1 = lr0 + 8;   // local query rows

    const int nkb = qb + 1;
    for (int kb = 0; kb < nkb; kb++) {
        if (kb + 1 < nkb) {
            flash_loadKV(sb + ((kb + 1) & 1) * FKVSZ,
                         kh, kl, vf, rowK, col0, kb + 1, tid);
            asm volatile("cp.async.wait_group 1;" ::: "memory");
        } else {
            asm volatile("cp.async.wait_group 0;" ::: "memory");
        }
        __syncthreads();

        const uint32_t Kb = sb + (kb & 1) * FKVSZ;

        // S = Q K^T (3-product split-bf16)
        float s[8][4];
        #pragma unroll
        for (int j = 0; j < 8; j++)
            #pragma unroll
            for (int r = 0; r < 4; r++) s[j][r] = 0.f;

        #pragma unroll
        for (int kt = 0; kt < 4; kt++) {
            #pragma unroll
            for (int p = 0; p < 4; p++) {
                uint32_t kboff = (uint32_t)((p * 16 + (l & 7) + ((l >> 4) << 3)) * FSTR
                                            + ((l >> 3) & 1) * 16 + kt * 32);
                uint32_t khb[4], klb[4];
                ldx4(khb, Kb + kboff);
                ldx4(klb, Kb + FTILE + kboff);
                #pragma unroll
                for (int sub = 0; sub < 2; sub++) {
                    float* d = s[p * 2 + sub];
                    const uint32_t b0 = khb[sub * 2], b1 = khb[sub * 2 + 1];
                    mma_bf16(d, qhf[kt], b0, b1);
                    mma_bf16(d, qhf[kt], klb[sub * 2], klb[sub * 2 + 1]);
                    mma_bf16(d, qlf[kt], b0, b1);
                }
            }
        }

        // causal mask on diagonal block (raw scores; positive scale commutes)
        if (kb == qb) {
            #pragma unroll
            for (int j = 0; j < 8; j++) {
                const int c0 = j * 8 + t * 2, c1 = c0 + 1;
                if (c0 > lr0) s[j][0] = NEG_INF;
                if (c1 > lr0) s[j][1] = NEG_INF;
                if (c0 > lr1) s[j][2] = NEG_INF;
                if (c1 > lr1) s[j][3] = NEG_INF;
            }
        }

        // online softmax; CS = 0.125*log2(e) folded into the ex2 FFMA
        const float CS = 0.18033688011112042f;
        float rm0 = NEG_INF, rm1 = NEG_INF;
        #pragma unroll
        for (int j = 0; j < 8; j++) {
            rm0 = fmaxf(rm0, fmaxf(s[j][0], s[j][1]));
            rm1 = fmaxf(rm1, fmaxf(s[j][2], s[j][3]));
        }
        rm0 = fmaxf(rm0, __shfl_xor_sync(0xffffffffu, rm0, 1));
        rm0 = fmaxf(rm0, __shfl_xor_sync(0xffffffffu, rm0, 2));
        rm1 = fmaxf(rm1, __shfl_xor_sync(0xffffffffu, rm1, 1));
        rm1 = fmaxf(rm1, __shfl_xor_sync(0xffffffffu, rm1, 2));
        rm0 *= CS;                       // scale AFTER reduction
        rm1 *= CS;

        const float mn0 = fmaxf(m0, rm0), mn1 = fmaxf(m1, rm1);
        const float al0 = ex2f(m0 - mn0), al1 = ex2f(m1 - mn1);
        m0 = mn0; m1 = mn1;

        float sum0 = 0.f, sum1 = 0.f;
        #pragma unroll
        for (int j = 0; j < 8; j++) {
            s[j][0] = ex2f(fmaf(s[j][0], CS, -mn0));
            s[j][1] = ex2f(fmaf(s[j][1], CS, -mn0));
            s[j][2] = ex2f(fmaf(s[j][2], CS, -mn1));
            s[j][3] = ex2f(fmaf(s[j][3], CS, -mn1));
            sum0 += s[j][0] + s[j][1];
            sum1 += s[j][2] + s[j][3];
        }
        sum0 += __shfl_xor_sync(0xffffffffu, sum0, 1);
        sum0 += __shfl_xor_sync(0xffffffffu, sum0, 2);
        sum1 += __shfl_xor_sync(0xffffffffu, sum1, 1);
        sum1 += __shfl_xor_sync(0xffffffffu, sum1, 2);
        sl0 = sl0 * al0 + sum0;
        sl1 = sl1 * al1 + sum1;

        #pragma unroll
        for (int j = 0; j < 8; j++) {
            o[j][0] *= al0; o[j][1] *= al0;
            o[j][2] *= al1; o[j][3] *= al1;
        }

        // O += P V  (SINGLE fp16 product: P packed fp16, V fp16 in smem)
        #pragma unroll
        for (int kt = 0; kt < 4; kt++) {
            uint32_t phf[4];
            {
                const int j0 = 2 * kt, j1 = 2 * kt + 1;
                phf[0] = packhf(s[j0][0], s[j0][1]);
                phf[1] = packhf(s[j0][2], s[j0][3]);
                phf[2] = packhf(s[j1][0], s[j1][1]);
                phf[3] = packhf(s[j1][2], s[j1][3]);
            }
            #pragma unroll
            for (int p = 0; p < 4; p++) {
                uint32_t voff = (uint32_t)((kt * 16 + ((l >> 3) & 1) * 8 + (l & 7)) * FSTR
                                           + p * 32 + ((l >> 4) << 4));
                uint32_t vb[4];
                ldx4t(vb, Kb + 2 * FTILE + voff);
                #pragma unroll
                for (int sub = 0; sub < 2; sub++)
                    mma_f16(o[p * 2 + sub], phf, vb[sub * 2], vb[sub * 2 + 1]);
            }
        }
        __syncthreads();
    }

    // Epilogue: normalize, split to bf16 hi/lo, store
    const float inv0 = 1.f / sl0, inv1 = 1.f / sl1;
    const size_t r0o = (rowQ + lr0) * EMB + col0;
    const size_t r1o = (rowQ + lr1) * EMB + col0;
    #pragma unroll
    for (int j = 0; j < 8; j++) {
        const int c = j * 8 + t * 2;
        float v0 = o[j][0] * inv0, v1 = o[j][1] * inv0;
        float v2 = o[j][2] * inv1, v3 = o[j][3] * inv1;
        uint32_t h0 = packbf(v0, v1);
        uint32_t l0 = packbf(v0 - bfloat_lo(h0), v1 - bfloat_hi(h0));
        uint32_t h1 = packbf(v2, v3);
        uint32_t l1 = packbf(v2 - bfloat_lo(h1), v3 - bfloat_hi(h1));
        *(uint32_t*)(ah + r0o + c) = h0;
        *(uint32_t*)(al + r0o + c) = l0;
        *(uint32_t*)(ah + r1o + c) = h1;
        *(uint32_t*)(al + r1o + c) = l1;
    }
}

// ---------------------------------------------------------------------------
// Launch
// ---------------------------------------------------------------------------
extern "C" void kernel_launch(void* const* d_in, const int* in_sizes, int n_in,
                              void* d_out, int out_size)
{
    const float* x  = (const float*)d_in[0];
    const float* W[4] = { (const float*)d_in[1], (const float*)d_in[2],
                          (const float*)d_in[3], (const float*)d_in[4] };
    float* out = (float*)d_out;

    void *pQ, *pK, *pV, *pxh, *pxl, *pah, *pal, *pwh, *pwl;
    cudaGetSymbolAddress(&pQ, g_Qp);
    cudaGetSymbolAddress(&pK, g_Kp);
    cudaGetSymbolAddress(&pV, g_Vp);
    cudaGetSymbolAddress(&pxh, g_xh);
    cudaGetSymbolAddress(&pxl, g_xl);
    cudaGetSymbolAddress(&pah, g_ah);
    cudaGetSymbolAddress(&pal, g_al);
    cudaGetSymbolAddress(&pwh, g_wh);
    cudaGetSymbolAddress(&pwl, g_wl);

    cudaFuncSetAttribute(gemm_qkv_kernel,
                         cudaFuncAttributeMaxDynamicSharedMemorySize, GEMM_SMEM);
    cudaFuncSetAttribute(gemm_out_kernel,
                         cudaFuncAttributeMaxDynamicSharedMemorySize, GEMM_SMEM);
    cudaFuncSetAttribute(flash_hmma_kernel,
                         cudaFuncAttributeMaxDynamicSharedMemorySize, FSMEM);

    __nv_bfloat16* xh = (__nv_bfloat16*)pxh;
    __nv_bfloat16* xl = (__nv_bfloat16*)pxl;
    __nv_bfloat16* ah = (__nv_bfloat16*)pah;
    __nv_bfloat16* al = (__nv_bfloat16*)pal;
    __nv_bfloat16* wh = (__nv_bfloat16*)pwh;
    __nv_bfloat16* wl = (__nv_bfloat16*)pwl;

    // fp32 scratch aliased: Q/K as (hi, lo) bf16 pairs; V as fp16 single
    __nv_bfloat16* qhp = (__nv_bfloat16*)pQ; __nv_bfloat16* qlp = qhp + NELEM;
    __nv_bfloat16* khp = (__nv_bfloat16*)pK; __nv_bfloat16* klp = khp + NELEM;
    __half* vfp = (__half*)pV;

    // 1) split x into bf16 hi/lo
    split_kernel<<<NELEM / 4 / 256, 256>>>(x, xh, xl, NELEM);

    // 2) transpose+split the four weight matrices
    dim3 wGrid(EMB / 32, EMB / 32), wBlk(32, 8);
    for (int i = 0; i < 4; i++)
        wsplit_kernel<<<wGrid, wBlk>>>(W[i], wh + (size_t)i * EMB * EMB,
                                       wl + (size_t)i * EMB * EMB);

    // 3) fused Q/K/V projections (Q,K bf16 split; V fp16)
    dim3 gGrid(3 * EMB / 128, MROWS / 128);   // (24, 64)
    gemm_qkv_kernel<<<gGrid, 256, GEMM_SMEM>>>(
        xh, xl, wh, wl, qhp, qlp, khp, klp, vfp);

    // 4) causal flash attention (BR=64, fp16 PV) -> split ah/al directly
    dim3 fGrid(SEQ / 64, HEADS, BATCH);   // (32, 16, 4)
    flash_hmma_kernel<<<fGrid, 128, FSMEM>>>(qhp, qlp, khp, klp, vfp, ah, al);

    // 5) final projection (fp32 out)
    dim3 oGrid(EMB / 128, MROWS / 128);   // (8, 64)
    gemm_out_kernel<<<oGrid, 256, GEMM_SMEM>>>(
        ah, al, wh + 3 * (size_t)EMB * EMB, wl + 3 * (size_t)EMB * EMB, out);
}